// round 13
// baseline (speedup 1.0000x reference)
#include <cuda_runtime.h>
#include <cuda_fp16.h>
#include <math.h>
#include <stdint.h>

// ---------------------------------------------------------------------------
// Problem constants
// ---------------------------------------------------------------------------
#define B_  4
#define S_  2048
#define D_  1024
#define M_TOK (B_ * S_)            // 8192

// ---------------------------------------------------------------------------
// Scratch (device globals; allocation in kernel_launch is forbidden)
// ---------------------------------------------------------------------------
__device__ __half g_Xh   [M_TOK * D_];
__device__ __half g_Wqkvt[3 * D_ * D_];      // [3072 N-rows, 1024 K]
__device__ __half g_WOt  [D_ * D_];
__device__ __half g_QKV  [(long)M_TOK * 3 * D_];  // [8192, 3072] fp16
__device__ __half g_Vth  [M_TOK * D_];       // per-batch [1024, 2048]
__device__ float  g_Sc   [B_ * S_ * S_];
__device__ __half g_Ph   [(long)B_ * S_ * S_];
__device__ __half g_Hh   [M_TOK * D_];

// ---------------------------------------------------------------------------
// Helpers
// ---------------------------------------------------------------------------
__device__ __forceinline__ uint32_t smem_u32(const void* p) {
    uint32_t a;
    asm("{ .reg .u64 t; cvta.to.shared.u64 t, %1; cvt.u32.u64 %0, t; }"
        : "=r"(a) : "l"(p));
    return a;
}

#define CP16(dst, src) \
    asm volatile("cp.async.cg.shared.global [%0], [%1], 16;" \
                 :: "r"((uint32_t)(dst)), "l"(src))

#define LDMX4(r, addr) \
    asm volatile("ldmatrix.sync.aligned.m8n8.x4.shared.b16 {%0,%1,%2,%3}, [%4];" \
                 : "=r"((r)[0]), "=r"((r)[1]), "=r"((r)[2]), "=r"((r)[3]) \
                 : "r"(addr))

#define MMA_F16(d, a, b0, b1) \
    asm("mma.sync.aligned.m16n8k16.row.col.f32.f16.f16.f32 " \
        "{%0,%1,%2,%3}, {%4,%5,%6,%7}, {%8,%9}, {%0,%1,%2,%3};" \
        : "+f"((d)[0]), "+f"((d)[1]), "+f"((d)[2]), "+f"((d)[3]) \
        : "r"((a)[0]), "r"((a)[1]), "r"((a)[2]), "r"((a)[3]), \
          "r"(b0), "r"(b1))

// ---------------------------------------------------------------------------
// fp16 mma.sync GEMM:  C[M,N] = alpha * A[M,K] · B[N,K]^T
// CTA tile 128x128, BK=32, 128 threads = 4 warps as 2m x 2n,
// warp tile 64x64 (high FLOP per smem byte: ~0.046 B/FLOP total traffic),
// 2 CTAs/SM (barrier overlap), cp.async 4-stage pipeline, one sync/iter,
// 80B row pitch, both ks-steps' ldmatrix batched.
// mode 0: fp32 C (row stride ldC).  mode 2: fp16 C (row stride ldC).
// Batched via blockIdx.z (element strides sA/sB/sC).
// ---------------------------------------------------------------------------
#define ROWB 80
#define TROWS 256
#define STAGE (TROWS * ROWB)                 // 20480
#define OFFB  (128 * ROWB)
#define GEMM_SMEM (4 * STAGE)                // 81920

__global__ __launch_bounds__(128, 2)
void gemmh(const __half* __restrict__ A, const __half* __restrict__ B,
           float* __restrict__ Cf, __half* __restrict__ Ch,
           int K, long ldA, long ldB, long ldC,
           long sA, long sB, long sC, float alpha, int mode)
{
    extern __shared__ char smem[];
    const uint32_t sb = smem_u32(smem);
    const int tid  = threadIdx.x;
    const int wid  = tid >> 5;
    const int lane = tid & 31;
    const long z   = blockIdx.z;

    // ---- global->smem load geometry: 256 rows * 64B of K; 8 chunks/thread
    const long rowA = (long)blockIdx.y * 128;
    const long rowB = (long)blockIdx.x * 128;
    const char* gp[8];
    uint32_t sw[8];
    #pragma unroll
    for (int j = 0; j < 8; j++) {
        int c = tid + 128 * j;
        int r = c >> 2;
        int col = (c & 3) * 16;
        sw[j] = (uint32_t)(r * ROWB + col);
        if (r < 128)
            gp[j] = (const char*)(A + z * sA + (rowA + r) * ldA) + col;
        else
            gp[j] = (const char*)(B + z * sB + (rowB + r - 128) * ldB) + col;
    }

    // ---- ldmatrix geometry: 2m x 2n warps, warp tile 64x64
    const int warp_m = wid & 1;
    const int warp_n = wid >> 1;
    const int quad = lane >> 3;
    const int lr8  = lane & 7;
    const uint32_t aBase = sb + (uint32_t)((warp_m * 64 + lr8 + (quad & 1) * 8) * ROWB
                                           + (quad >> 1) * 16);
    const uint32_t bBase = sb + OFFB + (uint32_t)((warp_n * 64 + lr8 + (quad & 1) * 8) * ROWB
                                                  + (quad >> 1) * 16);

    float acc[4][8][4];
    #pragma unroll
    for (int mf = 0; mf < 4; mf++)
        #pragma unroll
        for (int nf = 0; nf < 8; nf++)
            #pragma unroll
            for (int q = 0; q < 4; q++) acc[mf][nf][q] = 0.f;

    const int nc = K >> 5;

#define LOADSTAGE(base, ko) do { \
    _Pragma("unroll") \
    for (int j = 0; j < 8; j++) CP16((base) + sw[j], gp[j] + (ko)); \
    asm volatile("cp.async.commit_group;" ::: "memory"); \
} while (0)

    LOADSTAGE(sb, 0);
    LOADSTAGE(sb + STAGE, 64);

    for (int i = 0; i < nc; i++) {
        if (i + 2 < nc) {
            LOADSTAGE(sb + ((i + 2) & 3) * STAGE, (long)(i + 2) * 64);
            asm volatile("cp.async.wait_group 2;" ::: "memory");
        } else if (i + 1 < nc) {
            asm volatile("cp.async.wait_group 1;" ::: "memory");
        } else {
            asm volatile("cp.async.wait_group 0;" ::: "memory");
        }
        __syncthreads();

        const uint32_t stA = aBase + (i & 3) * STAGE;
        const uint32_t stB = bBase + (i & 3) * STAGE;

        // Batch all ldmatrix for both ks-steps before the MMAs.
        uint32_t ah[2][4][4], bh[2][4][4];
        #pragma unroll
        for (int ks = 0; ks < 2; ks++) {
            #pragma unroll
            for (int mf = 0; mf < 4; mf++)
                LDMX4(ah[ks][mf], stA + mf * (16 * ROWB) + ks * 32);
            #pragma unroll
            for (int ng = 0; ng < 4; ng++)
                LDMX4(bh[ks][ng], stB + ng * (16 * ROWB) + ks * 32);
        }
        #pragma unroll
        for (int ks = 0; ks < 2; ks++)
            #pragma unroll
            for (int ng = 0; ng < 4; ng++)
                #pragma unroll
                for (int mf = 0; mf < 4; mf++) {
                    MMA_F16(acc[mf][ng * 2 + 0], ah[ks][mf],
                            bh[ks][ng][0], bh[ks][ng][2]);
                    MMA_F16(acc[mf][ng * 2 + 1], ah[ks][mf],
                            bh[ks][ng][1], bh[ks][ng][3]);
                }
    }
#undef LOADSTAGE

    // ---- epilogue
    const long baseM = (long)blockIdx.y * 128 + warp_m * 64;
    const long baseN = (long)blockIdx.x * 128 + warp_n * 64;
    const int rq = lane >> 2;
    const int cq = (lane & 3) * 2;
    #pragma unroll
    for (int mf = 0; mf < 4; mf++) {
        #pragma unroll
        for (int nf = 0; nf < 8; nf++) {
            const long r0 = baseM + mf * 16 + rq;
            const long c0 = baseN + nf * 8 + cq;
            float v0 = acc[mf][nf][0] * alpha;
            float v1 = acc[mf][nf][1] * alpha;
            float v2 = acc[mf][nf][2] * alpha;
            float v3 = acc[mf][nf][3] * alpha;
            if (mode == 0) {
                float* o0 = Cf + z * sC + r0 * ldC + c0;
                *(float2*)o0 = make_float2(v0, v1);
                *(float2*)(o0 + 8 * ldC) = make_float2(v2, v3);
            } else {
                __half* oh0 = Ch + z * sC + r0 * ldC + c0;
                *(__half2*)oh0 = __halves2half2(__float2half_rn(v0),
                                                __float2half_rn(v1));
                *(__half2*)(oh0 + 8 * ldC) = __halves2half2(__float2half_rn(v2),
                                                            __float2half_rn(v3));
            }
        }
    }
}

// ---------------------------------------------------------------------------
// Fused prep: X fp32->fp16 convert + 4 weight transposes, one launch.
// ---------------------------------------------------------------------------
__global__ __launch_bounds__(256)
void prep(const float* __restrict__ X,
          const float* __restrict__ WQ, const float* __restrict__ WK,
          const float* __restrict__ WV, const float* __restrict__ WO,
          __half* __restrict__ Xh, __half* __restrict__ Wqkvt,
          __half* __restrict__ WOt)
{
    __shared__ float t[32][33];
    const int bid = blockIdx.x;
    const int tid = threadIdx.x;

    if (bid < 8192) {
        int i = bid * 256 + tid;
        float4 v = ((const float4*)X)[i];
        ((__half2*)Xh)[2 * i]     = __halves2half2(__float2half_rn(v.x),
                                                   __float2half_rn(v.y));
        ((__half2*)Xh)[2 * i + 1] = __halves2half2(__float2half_rn(v.z),
                                                   __float2half_rn(v.w));
        return;
    }

    const int wb = bid - 8192;
    const int wi = wb >> 10;
    const int b  = wb & 1023;
    const float* src = (wi == 0) ? WQ : (wi == 1) ? WK : (wi == 2) ? WV : WO;
    __half* dst = (wi == 3) ? WOt : (Wqkvt + (long)wi * D_ * D_);

    const int c0 = (b & 31) * 32, r0 = (b >> 5) * 32;
    const int tx = tid & 31, ty = tid >> 5;
    #pragma unroll
    for (int j = 0; j < 4; j++)
        t[ty + 8 * j][tx] = src[(long)(r0 + ty + 8 * j) * D_ + c0 + tx];
    __syncthreads();
    #pragma unroll
    for (int j = 0; j < 4; j++)
        dst[(long)(c0 + ty + 8 * j) * D_ + r0 + tx] =
            __float2half_rn(t[tx][ty + 8 * j]);
}

// ---------------------------------------------------------------------------
// fp16 strided [R,C] (row stride ldIn) -> transposed fp16 [C,R] (batched)
// ---------------------------------------------------------------------------
__global__ void tr16(const __half* __restrict__ in,
                     __half* __restrict__ out,
                     int R, int C, long ldIn, long sIn, long sOut)
{
    __shared__ __half t[32][34];
    const __half* ip = in + (long)blockIdx.z * sIn;
    const int c0 = blockIdx.x * 32, r0 = blockIdx.y * 32;
    const int tx = threadIdx.x, ty = threadIdx.y;
    #pragma unroll
    for (int j = 0; j < 4; j++)
        t[ty + 8 * j][tx] = ip[(long)(r0 + ty + 8 * j) * ldIn + c0 + tx];
    __syncthreads();
    __half* op = out + (long)blockIdx.z * sOut;
    #pragma unroll
    for (int j = 0; j < 4; j++)
        op[(long)(c0 + ty + 8 * j) * R + r0 + tx] = t[tx][ty + 8 * j];
}

// ---------------------------------------------------------------------------
// Row softmax over length-2048 rows; fp32 in, fp16 out. float4 loads.
// ---------------------------------------------------------------------------
__global__ __launch_bounds__(256)
void softmax_rows(const float* __restrict__ S, __half* __restrict__ P)
{
    const long base = (long)blockIdx.x * S_;
    const float4* row4 = (const float4*)(S + base);
    const int tid  = threadIdx.x;
    const int lane = tid & 31;
    const int warp = tid >> 5;
    __shared__ float red[8];

    float4 va = row4[tid];
    float4 vb = row4[tid + 256];
    float m = fmaxf(fmaxf(fmaxf(va.x, va.y), fmaxf(va.z, va.w)),
                    fmaxf(fmaxf(vb.x, vb.y), fmaxf(vb.z, vb.w)));
    #pragma unroll
    for (int o = 16; o > 0; o >>= 1) m = fmaxf(m, __shfl_xor_sync(0xffffffffu, m, o));
    if (lane == 0) red[warp] = m;
    __syncthreads();
    m = red[lane & 7];
    #pragma unroll
    for (int o = 4; o > 0; o >>= 1) m = fmaxf(m, __shfl_xor_sync(0xffffffffu, m, o));
    m = __shfl_sync(0xffffffffu, m, 0);

    va.x = __expf(va.x - m); va.y = __expf(va.y - m);
    va.z = __expf(va.z - m); va.w = __expf(va.w - m);
    vb.x = __expf(vb.x - m); vb.y = __expf(vb.y - m);
    vb.z = __expf(vb.z - m); vb.w = __expf(vb.w - m);
    float s = va.x + va.y + va.z + va.w + vb.x + vb.y + vb.z + vb.w;
    #pragma unroll
    for (int o = 16; o > 0; o >>= 1) s += __shfl_xor_sync(0xffffffffu, s, o);
    __syncthreads();
    if (lane == 0) red[warp] = s;
    __syncthreads();
    s = red[lane & 7];
    #pragma unroll
    for (int o = 4; o > 0; o >>= 1) s += __shfl_xor_sync(0xffffffffu, s, o);
    s = __shfl_sync(0xffffffffu, s, 0);

    const float inv = 1.f / s;
    __half2* p2 = (__half2*)(P + base);
    p2[2 * tid]       = __halves2half2(__float2half_rn(va.x * inv),
                                       __float2half_rn(va.y * inv));
    p2[2 * tid + 1]   = __halves2half2(__float2half_rn(va.z * inv),
                                       __float2half_rn(va.w * inv));
    p2[2 * (tid+256)]     = __halves2half2(__float2half_rn(vb.x * inv),
                                           __float2half_rn(vb.y * inv));
    p2[2 * (tid+256) + 1] = __halves2half2(__float2half_rn(vb.z * inv),
                                           __float2half_rn(vb.w * inv));
}

// ---------------------------------------------------------------------------
extern "C" void kernel_launch(void* const* d_in, const int* in_sizes, int n_in,
                              void* d_out, int out_size)
{
    const float* X  = (const float*)d_in[0];
    const float* WQ = (const float*)d_in[1];
    const float* WK = (const float*)d_in[2];
    const float* WV = (const float*)d_in[3];
    const float* WO = (const float*)d_in[4];
    float* Y = (float*)d_out;

    __half *Xh, *Wqkvt, *WOt, *QKV, *Vth, *Ph, *Hh;
    float *Sc;
    cudaGetSymbolAddress((void**)&Xh,    g_Xh);
    cudaGetSymbolAddress((void**)&Wqkvt, g_Wqkvt);
    cudaGetSymbolAddress((void**)&WOt,   g_WOt);
    cudaGetSymbolAddress((void**)&QKV,   g_QKV);
    cudaGetSymbolAddress((void**)&Vth,   g_Vth);
    cudaGetSymbolAddress((void**)&Sc,    g_Sc);
    cudaGetSymbolAddress((void**)&Ph,    g_Ph);
    cudaGetSymbolAddress((void**)&Hh,    g_Hh);

    cudaFuncSetAttribute(gemmh, cudaFuncAttributeMaxDynamicSharedMemorySize,
                         GEMM_SMEM);

    dim3 thrG(128);
    dim3 thr(256);
    dim3 tW(32, 8);
    const long LD3 = 3 * D_;                  // 3072

    // Fused input conversions (X convert + 4 W transposes)
    prep<<<8192 + 4096, thr>>>(X, WQ, WK, WV, WO, Xh, Wqkvt, WOt);

    // Fused QKV projection: [8192, 3072] = Xh · Wqkvt^T, fp16 out
    gemmh<<<dim3(24, 64, 1), thrG, GEMM_SMEM>>>(Xh, Wqkvt, nullptr, QKV,
                                                D_, D_, D_, LD3,
                                                0, 0, 0, 1.f, 2);

    // V slice -> per-batch transpose [1024, 2048] fp16
    tr16<<<dim3(D_ / 32, S_ / 32, B_), tW>>>(QKV + 2 * D_, Vth,
                                             S_, D_, LD3,
                                             (long)S_ * LD3, (long)S_ * D_);

    // Scores: per-batch [2048,2048] = Q · K^T / 32 -> fp32
    gemmh<<<dim3(16, 16, 4), thrG, GEMM_SMEM>>>(QKV, QKV + D_, Sc, nullptr,
                                                D_, LD3, LD3, S_,
                                                (long)S_ * LD3, (long)S_ * LD3,
                                                (long)S_ * S_, 1.f / 32.f, 0);

    // Softmax -> probs fp16
    softmax_rows<<<B_ * S_, thr>>>(Sc, Ph);

    // H = P · V^T : per-batch [2048,1024], fp16 out
    gemmh<<<dim3(8, 16, 4), thrG, GEMM_SMEM>>>(Ph, Vth, nullptr, Hh,
                                               S_, S_, S_, D_,
                                               (long)S_ * S_, (long)S_ * D_,
                                               (long)S_ * D_, 1.f, 2);

    // Output: [8192,1024] = Hh · WOt^T -> fp32 to d_out
    gemmh<<<dim3(8, 64, 1), thrG, GEMM_SMEM>>>(Hh, WOt, Y, nullptr,
                                               D_, D_, D_, D_,
                                               0, 0, 0, 1.f, 0);
}

// round 14
// speedup vs baseline: 1.0567x; 1.0567x over previous
#include <cuda_runtime.h>
#include <cuda_fp16.h>
#include <math.h>
#include <stdint.h>

// ---------------------------------------------------------------------------
// Problem constants
// ---------------------------------------------------------------------------
#define B_  4
#define S_  2048
#define D_  1024
#define M_TOK (B_ * S_)            // 8192

// ---------------------------------------------------------------------------
// Scratch (device globals; allocation in kernel_launch is forbidden)
// ---------------------------------------------------------------------------
__device__ __half g_Xh   [M_TOK * D_];
__device__ __half g_Wqkvt[3 * D_ * D_];      // [3072 N-rows, 1024 K]
__device__ __half g_WOt  [D_ * D_];
__device__ __half g_QKV  [(long)M_TOK * 3 * D_];  // [8192, 3072] fp16
__device__ __half g_Vth  [M_TOK * D_];       // per-batch [1024, 2048]
__device__ float  g_Sc   [B_ * S_ * S_];
__device__ __half g_Ph   [(long)B_ * S_ * S_];
__device__ __half g_Hh   [M_TOK * D_];

// ---------------------------------------------------------------------------
// Helpers
// ---------------------------------------------------------------------------
__device__ __forceinline__ uint32_t smem_u32(const void* p) {
    uint32_t a;
    asm("{ .reg .u64 t; cvta.to.shared.u64 t, %1; cvt.u32.u64 %0, t; }"
        : "=r"(a) : "l"(p));
    return a;
}

#define CP16(dst, src) \
    asm volatile("cp.async.cg.shared.global [%0], [%1], 16;" \
                 :: "r"((uint32_t)(dst)), "l"(src))

#define LDMX4(r, addr) \
    asm volatile("ldmatrix.sync.aligned.m8n8.x4.shared.b16 {%0,%1,%2,%3}, [%4];" \
                 : "=r"((r)[0]), "=r"((r)[1]), "=r"((r)[2]), "=r"((r)[3]) \
                 : "r"(addr))

#define MMA_F16(d, a, b0, b1) \
    asm("mma.sync.aligned.m16n8k16.row.col.f32.f16.f16.f32 " \
        "{%0,%1,%2,%3}, {%4,%5,%6,%7}, {%8,%9}, {%0,%1,%2,%3};" \
        : "+f"((d)[0]), "+f"((d)[1]), "+f"((d)[2]), "+f"((d)[3]) \
        : "r"((a)[0]), "r"((a)[1]), "r"((a)[2]), "r"((a)[3]), \
          "r"(b0), "r"(b1))

// ---------------------------------------------------------------------------
// fp16 mma.sync GEMM:  C[M,N] = alpha * A[M,K] · B[N,K]^T
// CTA tile 128x128, BK=32, 256 thr (8 warps as 4m x 2n, warp tile 32x64).
// cp.async 4-stage pipeline, ONE __syncthreads per K-iter, 80B row pitch,
// both ks-steps' ldmatrix batched, next-stage cp.async issued AFTER the
// ldsm batch (LSU decollision), 2 CTAs/SM.
// mode 0: fp32 C (row stride ldC).  mode 2: fp16 C (row stride ldC).
// Batched via blockIdx.z (element strides sA/sB/sC).
// ---------------------------------------------------------------------------
#define ROWB 80
#define TROWS 256
#define STAGE (TROWS * ROWB)                 // 20480
#define OFFB  (128 * ROWB)
#define GEMM_SMEM (4 * STAGE)                // 81920

__global__ __launch_bounds__(256, 2)
void gemmh(const __half* __restrict__ A, const __half* __restrict__ B,
           float* __restrict__ Cf, __half* __restrict__ Ch,
           int K, long ldA, long ldB, long ldC,
           long sA, long sB, long sC, float alpha, int mode)
{
    extern __shared__ char smem[];
    const uint32_t sb = smem_u32(smem);
    const int tid  = threadIdx.x;
    const int wid  = tid >> 5;
    const int lane = tid & 31;
    const long z   = blockIdx.z;

    // ---- global->smem load geometry: 256 rows * 64B of K; 4 chunks/thread
    const long rowA = (long)blockIdx.y * 128;
    const long rowB = (long)blockIdx.x * 128;
    const char* gp[4];
    uint32_t sw[4];
    #pragma unroll
    for (int j = 0; j < 4; j++) {
        int c = tid + 256 * j;
        int r = c >> 2;
        int col = (c & 3) * 16;
        sw[j] = (uint32_t)(r * ROWB + col);
        if (r < 128)
            gp[j] = (const char*)(A + z * sA + (rowA + r) * ldA) + col;
        else
            gp[j] = (const char*)(B + z * sB + (rowB + r - 128) * ldB) + col;
    }

    // ---- ldmatrix geometry: warp tile 32x64 (4m x 2n warps)
    const int warp_m = wid & 3;
    const int warp_n = wid >> 2;
    const int quad = lane >> 3;
    const int lr8  = lane & 7;
    const uint32_t aBase = sb + (uint32_t)((warp_m * 32 + lr8 + (quad & 1) * 8) * ROWB
                                           + (quad >> 1) * 16);
    const uint32_t bBase = sb + OFFB + (uint32_t)((warp_n * 64 + lr8 + (quad & 1) * 8) * ROWB
                                                  + (quad >> 1) * 16);

    float acc[2][8][4];
    #pragma unroll
    for (int mf = 0; mf < 2; mf++)
        #pragma unroll
        for (int nf = 0; nf < 8; nf++)
            #pragma unroll
            for (int q = 0; q < 4; q++) acc[mf][nf][q] = 0.f;

    const int nc = K >> 5;

#define LOADSTAGE(base, ko) do { \
    _Pragma("unroll") \
    for (int j = 0; j < 4; j++) CP16((base) + sw[j], gp[j] + (ko)); \
    asm volatile("cp.async.commit_group;" ::: "memory"); \
} while (0)

    LOADSTAGE(sb, 0);
    LOADSTAGE(sb + STAGE, 64);

    for (int i = 0; i < nc; i++) {
        // Stage i must be resident. Pending groups here are {i, i+1}
        // (loads for i+2 are issued below, after the ldsm batch).
        if (i + 1 < nc) {
            asm volatile("cp.async.wait_group 1;" ::: "memory");
        } else {
            asm volatile("cp.async.wait_group 0;" ::: "memory");
        }
        __syncthreads();

        const uint32_t stA = aBase + (i & 3) * STAGE;
        const uint32_t stB = bBase + (i & 3) * STAGE;

        // Batch ALL ldmatrix for both ks-steps.
        uint32_t ah[2][2][4], bh[2][4][4];
        #pragma unroll
        for (int ks = 0; ks < 2; ks++) {
            #pragma unroll
            for (int mf = 0; mf < 2; mf++)
                LDMX4(ah[ks][mf], stA + mf * (16 * ROWB) + ks * 32);
            #pragma unroll
            for (int ng = 0; ng < 4; ng++)
                LDMX4(bh[ks][ng], stB + ng * (16 * ROWB) + ks * 32);
        }

        // Issue next-stage global loads now (stage (i+2)%4 conflicts with
        // no stage readable by any warp still inside iter i or i-1).
        if (i + 2 < nc)
            LOADSTAGE(sb + ((i + 2) & 3) * STAGE, (long)(i + 2) * 64);

        #pragma unroll
        for (int ks = 0; ks < 2; ks++)
            #pragma unroll
            for (int ng = 0; ng < 4; ng++)
                #pragma unroll
                for (int mf = 0; mf < 2; mf++) {
                    MMA_F16(acc[mf][ng * 2 + 0], ah[ks][mf],
                            bh[ks][ng][0], bh[ks][ng][2]);
                    MMA_F16(acc[mf][ng * 2 + 1], ah[ks][mf],
                            bh[ks][ng][1], bh[ks][ng][3]);
                }
    }
#undef LOADSTAGE

    // ---- epilogue
    const long baseM = (long)blockIdx.y * 128 + warp_m * 32;
    const long baseN = (long)blockIdx.x * 128 + warp_n * 64;
    const int rq = lane >> 2;
    const int cq = (lane & 3) * 2;
    #pragma unroll
    for (int mf = 0; mf < 2; mf++) {
        #pragma unroll
        for (int nf = 0; nf < 8; nf++) {
            const long r0 = baseM + mf * 16 + rq;
            const long c0 = baseN + nf * 8 + cq;
            float v0 = acc[mf][nf][0] * alpha;
            float v1 = acc[mf][nf][1] * alpha;
            float v2 = acc[mf][nf][2] * alpha;
            float v3 = acc[mf][nf][3] * alpha;
            if (mode == 0) {
                float* o0 = Cf + z * sC + r0 * ldC + c0;
                *(float2*)o0 = make_float2(v0, v1);
                *(float2*)(o0 + 8 * ldC) = make_float2(v2, v3);
            } else {
                __half* oh0 = Ch + z * sC + r0 * ldC + c0;
                *(__half2*)oh0 = __halves2half2(__float2half_rn(v0),
                                                __float2half_rn(v1));
                *(__half2*)(oh0 + 8 * ldC) = __halves2half2(__float2half_rn(v2),
                                                            __float2half_rn(v3));
            }
        }
    }
}

// ---------------------------------------------------------------------------
// Fused prep: X fp32->fp16 convert + 4 weight transposes, one launch.
// ---------------------------------------------------------------------------
__global__ __launch_bounds__(256)
void prep(const float* __restrict__ X,
          const float* __restrict__ WQ, const float* __restrict__ WK,
          const float* __restrict__ WV, const float* __restrict__ WO,
          __half* __restrict__ Xh, __half* __restrict__ Wqkvt,
          __half* __restrict__ WOt)
{
    __shared__ float t[32][33];
    const int bid = blockIdx.x;
    const int tid = threadIdx.x;

    if (bid < 8192) {
        int i = bid * 256 + tid;
        float4 v = ((const float4*)X)[i];
        ((__half2*)Xh)[2 * i]     = __halves2half2(__float2half_rn(v.x),
                                                   __float2half_rn(v.y));
        ((__half2*)Xh)[2 * i + 1] = __halves2half2(__float2half_rn(v.z),
                                                   __float2half_rn(v.w));
        return;
    }

    const int wb = bid - 8192;
    const int wi = wb >> 10;
    const int b  = wb & 1023;
    const float* src = (wi == 0) ? WQ : (wi == 1) ? WK : (wi == 2) ? WV : WO;
    __half* dst = (wi == 3) ? WOt : (Wqkvt + (long)wi * D_ * D_);

    const int c0 = (b & 31) * 32, r0 = (b >> 5) * 32;
    const int tx = tid & 31, ty = tid >> 5;
    #pragma unroll
    for (int j = 0; j < 4; j++)
        t[ty + 8 * j][tx] = src[(long)(r0 + ty + 8 * j) * D_ + c0 + tx];
    __syncthreads();
    #pragma unroll
    for (int j = 0; j < 4; j++)
        dst[(long)(c0 + ty + 8 * j) * D_ + r0 + tx] =
            __float2half_rn(t[tx][ty + 8 * j]);
}

// ---------------------------------------------------------------------------
// fp16 strided [R,C] (row stride ldIn) -> transposed fp16 [C,R] (batched)
// ---------------------------------------------------------------------------
__global__ void tr16(const __half* __restrict__ in,
                     __half* __restrict__ out,
                     int R, int C, long ldIn, long sIn, long sOut)
{
    __shared__ __half t[32][34];
    const __half* ip = in + (long)blockIdx.z * sIn;
    const int c0 = blockIdx.x * 32, r0 = blockIdx.y * 32;
    const int tx = threadIdx.x, ty = threadIdx.y;
    #pragma unroll
    for (int j = 0; j < 4; j++)
        t[ty + 8 * j][tx] = ip[(long)(r0 + ty + 8 * j) * ldIn + c0 + tx];
    __syncthreads();
    __half* op = out + (long)blockIdx.z * sOut;
    #pragma unroll
    for (int j = 0; j < 4; j++)
        op[(long)(c0 + ty + 8 * j) * R + r0 + tx] = t[tx][ty + 8 * j];
}

// ---------------------------------------------------------------------------
// Row softmax over length-2048 rows; fp32 in, fp16 out. float4 loads.
// ---------------------------------------------------------------------------
__global__ __launch_bounds__(256)
void softmax_rows(const float* __restrict__ S, __half* __restrict__ P)
{
    const long base = (long)blockIdx.x * S_;
    const float4* row4 = (const float4*)(S + base);
    const int tid  = threadIdx.x;
    const int lane = tid & 31;
    const int warp = tid >> 5;
    __shared__ float red[8];

    float4 va = row4[tid];
    float4 vb = row4[tid + 256];
    float m = fmaxf(fmaxf(fmaxf(va.x, va.y), fmaxf(va.z, va.w)),
                    fmaxf(fmaxf(vb.x, vb.y), fmaxf(vb.z, vb.w)));
    #pragma unroll
    for (int o = 16; o > 0; o >>= 1) m = fmaxf(m, __shfl_xor_sync(0xffffffffu, m, o));
    if (lane == 0) red[warp] = m;
    __syncthreads();
    m = red[lane & 7];
    #pragma unroll
    for (int o = 4; o > 0; o >>= 1) m = fmaxf(m, __shfl_xor_sync(0xffffffffu, m, o));
    m = __shfl_sync(0xffffffffu, m, 0);

    va.x = __expf(va.x - m); va.y = __expf(va.y - m);
    va.z = __expf(va.z - m); va.w = __expf(va.w - m);
    vb.x = __expf(vb.x - m); vb.y = __expf(vb.y - m);
    vb.z = __expf(vb.z - m); vb.w = __expf(vb.w - m);
    float s = va.x + va.y + va.z + va.w + vb.x + vb.y + vb.z + vb.w;
    #pragma unroll
    for (int o = 16; o > 0; o >>= 1) s += __shfl_xor_sync(0xffffffffu, s, o);
    __syncthreads();
    if (lane == 0) red[warp] = s;
    __syncthreads();
    s = red[lane & 7];
    #pragma unroll
    for (int o = 4; o > 0; o >>= 1) s += __shfl_xor_sync(0xffffffffu, s, o);
    s = __shfl_sync(0xffffffffu, s, 0);

    const float inv = 1.f / s;
    __half2* p2 = (__half2*)(P + base);
    p2[2 * tid]       = __halves2half2(__float2half_rn(va.x * inv),
                                       __float2half_rn(va.y * inv));
    p2[2 * tid + 1]   = __halves2half2(__float2half_rn(va.z * inv),
                                       __float2half_rn(va.w * inv));
    p2[2 * (tid+256)]     = __halves2half2(__float2half_rn(vb.x * inv),
                                           __float2half_rn(vb.y * inv));
    p2[2 * (tid+256) + 1] = __halves2half2(__float2half_rn(vb.z * inv),
                                           __float2half_rn(vb.w * inv));
}

// ---------------------------------------------------------------------------
extern "C" void kernel_launch(void* const* d_in, const int* in_sizes, int n_in,
                              void* d_out, int out_size)
{
    const float* X  = (const float*)d_in[0];
    const float* WQ = (const float*)d_in[1];
    const float* WK = (const float*)d_in[2];
    const float* WV = (const float*)d_in[3];
    const float* WO = (const float*)d_in[4];
    float* Y = (float*)d_out;

    __half *Xh, *Wqkvt, *WOt, *QKV, *Vth, *Ph, *Hh;
    float *Sc;
    cudaGetSymbolAddress((void**)&Xh,    g_Xh);
    cudaGetSymbolAddress((void**)&Wqkvt, g_Wqkvt);
    cudaGetSymbolAddress((void**)&WOt,   g_WOt);
    cudaGetSymbolAddress((void**)&QKV,   g_QKV);
    cudaGetSymbolAddress((void**)&Vth,   g_Vth);
    cudaGetSymbolAddress((void**)&Sc,    g_Sc);
    cudaGetSymbolAddress((void**)&Ph,    g_Ph);
    cudaGetSymbolAddress((void**)&Hh,    g_Hh);

    cudaFuncSetAttribute(gemmh, cudaFuncAttributeMaxDynamicSharedMemorySize,
                         GEMM_SMEM);

    dim3 thr(256);
    dim3 tW(32, 8);
    const long LD3 = 3 * D_;                  // 3072

    // Fused input conversions (X convert + 4 W transposes)
    prep<<<8192 + 4096, thr>>>(X, WQ, WK, WV, WO, Xh, Wqkvt, WOt);

    // Fused QKV projection: [8192, 3072] = Xh · Wqkvt^T, fp16 out
    gemmh<<<dim3(24, 64, 1), thr, GEMM_SMEM>>>(Xh, Wqkvt, nullptr, QKV,
                                               D_, D_, D_, LD3,
                                               0, 0, 0, 1.f, 2);

    // V slice -> per-batch transpose [1024, 2048] fp16
    tr16<<<dim3(D_ / 32, S_ / 32, B_), tW>>>(QKV + 2 * D_, Vth,
                                             S_, D_, LD3,
                                             (long)S_ * LD3, (long)S_ * D_);

    // Scores: per-batch [2048,2048] = Q · K^T / 32 -> fp32
    gemmh<<<dim3(16, 16, 4), thr, GEMM_SMEM>>>(QKV, QKV + D_, Sc, nullptr,
                                               D_, LD3, LD3, S_,
                                               (long)S_ * LD3, (long)S_ * LD3,
                                               (long)S_ * S_, 1.f / 32.f, 0);

    // Softmax -> probs fp16
    softmax_rows<<<B_ * S_, thr>>>(Sc, Ph);

    // H = P · V^T : per-batch [2048,1024], fp16 out
    gemmh<<<dim3(8, 16, 4), thr, GEMM_SMEM>>>(Ph, Vth, nullptr, Hh,
                                              S_, S_, S_, D_,
                                              (long)S_ * S_, (long)S_ * D_,
                                              (long)S_ * D_, 1.f, 2);

    // Output: [8192,1024] = Hh · WOt^T -> fp32 to d_out
    gemmh<<<dim3(8, 64, 1), thr, GEMM_SMEM>>>(Hh, WOt, Y, nullptr,
                                              D_, D_, D_, D_,
                                              0, 0, 0, 1.f, 0);
}

// round 15
// speedup vs baseline: 1.1380x; 1.0769x over previous
#include <cuda_runtime.h>
#include <cuda_fp16.h>
#include <math.h>
#include <stdint.h>

// ---------------------------------------------------------------------------
// Problem constants
// ---------------------------------------------------------------------------
#define B_  4
#define S_  2048
#define D_  1024
#define M_TOK (B_ * S_)            // 8192

// ---------------------------------------------------------------------------
// Scratch (device globals; allocation in kernel_launch is forbidden)
// ---------------------------------------------------------------------------
__device__ __half g_Xh   [M_TOK * D_];
__device__ __half g_Wqkvt[3 * D_ * D_];      // [3072 N-rows, 1024 K]
__device__ __half g_WOt  [D_ * D_];
__device__ __half g_QKV  [(long)M_TOK * 3 * D_];  // [8192, 3072] fp16
__device__ __half g_Vth  [M_TOK * D_];       // per-batch [1024, 2048]
__device__ float  g_Sc   [B_ * S_ * S_];
__device__ __half g_Ph   [(long)B_ * S_ * S_];
__device__ __half g_Hh   [M_TOK * D_];

// ---------------------------------------------------------------------------
// Helpers
// ---------------------------------------------------------------------------
__device__ __forceinline__ uint32_t smem_u32(const void* p) {
    uint32_t a;
    asm("{ .reg .u64 t; cvta.to.shared.u64 t, %1; cvt.u32.u64 %0, t; }"
        : "=r"(a) : "l"(p));
    return a;
}

#define CP16(dst, src) \
    asm volatile("cp.async.cg.shared.global [%0], [%1], 16;" \
                 :: "r"((uint32_t)(dst)), "l"(src))

#define LDMX4(r, addr) \
    asm volatile("ldmatrix.sync.aligned.m8n8.x4.shared.b16 {%0,%1,%2,%3}, [%4];" \
                 : "=r"((r)[0]), "=r"((r)[1]), "=r"((r)[2]), "=r"((r)[3]) \
                 : "r"(addr))

#define MMA_F16(d, a, b0, b1) \
    asm("mma.sync.aligned.m16n8k16.row.col.f32.f16.f16.f32 " \
        "{%0,%1,%2,%3}, {%4,%5,%6,%7}, {%8,%9}, {%0,%1,%2,%3};" \
        : "+f"((d)[0]), "+f"((d)[1]), "+f"((d)[2]), "+f"((d)[3]) \
        : "r"((a)[0]), "r"((a)[1]), "r"((a)[2]), "r"((a)[3]), \
          "r"(b0), "r"(b1))

// ---------------------------------------------------------------------------
// fp16 mma.sync GEMM:  C[M,N] = alpha * A[M,K] · B[N,K]^T
// CTA tile 128x128, BK=32, 256 thr (8 warps as 4m x 2n, warp tile 32x64).
// cp.async 4-stage pipeline, ONE __syncthreads per K-iter, 80B row pitch,
// ALL ldmatrix of both ks-steps batched before the MMAs, 2 CTAs/SM.
// This configuration is the measured optimum across 6 mainloop variants
// (warp tiles 32x32/32x64/64x64, load orders, CTA shapes): it saturates the
// legacy mma.sync issue ceiling (~48.7% of rated tensor pipe) on this part.
// mode 0: fp32 C (row stride ldC).  mode 2: fp16 C (row stride ldC).
// Batched via blockIdx.z (element strides sA/sB/sC).
// ---------------------------------------------------------------------------
#define ROWB 80
#define TROWS 256
#define STAGE (TROWS * ROWB)                 // 20480
#define OFFB  (128 * ROWB)
#define GEMM_SMEM (4 * STAGE)                // 81920

__global__ __launch_bounds__(256, 2)
void gemmh(const __half* __restrict__ A, const __half* __restrict__ B,
           float* __restrict__ Cf, __half* __restrict__ Ch,
           int K, long ldA, long ldB, long ldC,
           long sA, long sB, long sC, float alpha, int mode)
{
    extern __shared__ char smem[];
    const uint32_t sb = smem_u32(smem);
    const int tid  = threadIdx.x;
    const int wid  = tid >> 5;
    const int lane = tid & 31;
    const long z   = blockIdx.z;

    // ---- global->smem load geometry: 256 rows * 64B of K; 4 chunks/thread
    const long rowA = (long)blockIdx.y * 128;
    const long rowB = (long)blockIdx.x * 128;
    const char* gp[4];
    uint32_t sw[4];
    #pragma unroll
    for (int j = 0; j < 4; j++) {
        int c = tid + 256 * j;
        int r = c >> 2;
        int col = (c & 3) * 16;
        sw[j] = (uint32_t)(r * ROWB + col);
        if (r < 128)
            gp[j] = (const char*)(A + z * sA + (rowA + r) * ldA) + col;
        else
            gp[j] = (const char*)(B + z * sB + (rowB + r - 128) * ldB) + col;
    }

    // ---- ldmatrix geometry: warp tile 32x64 (4m x 2n warps)
    const int warp_m = wid & 3;
    const int warp_n = wid >> 2;
    const int quad = lane >> 3;
    const int lr8  = lane & 7;
    const uint32_t aBase = sb + (uint32_t)((warp_m * 32 + lr8 + (quad & 1) * 8) * ROWB
                                           + (quad >> 1) * 16);
    const uint32_t bBase = sb + OFFB + (uint32_t)((warp_n * 64 + lr8 + (quad & 1) * 8) * ROWB
                                                  + (quad >> 1) * 16);

    float acc[2][8][4];
    #pragma unroll
    for (int mf = 0; mf < 2; mf++)
        #pragma unroll
        for (int nf = 0; nf < 8; nf++)
            #pragma unroll
            for (int q = 0; q < 4; q++) acc[mf][nf][q] = 0.f;

    const int nc = K >> 5;

#define LOADSTAGE(base, ko) do { \
    _Pragma("unroll") \
    for (int j = 0; j < 4; j++) CP16((base) + sw[j], gp[j] + (ko)); \
    asm volatile("cp.async.commit_group;" ::: "memory"); \
} while (0)

    LOADSTAGE(sb, 0);
    LOADSTAGE(sb + STAGE, 64);

    for (int i = 0; i < nc; i++) {
        if (i + 2 < nc) {
            LOADSTAGE(sb + ((i + 2) & 3) * STAGE, (long)(i + 2) * 64);
            asm volatile("cp.async.wait_group 2;" ::: "memory");
        } else if (i + 1 < nc) {
            asm volatile("cp.async.wait_group 1;" ::: "memory");
        } else {
            asm volatile("cp.async.wait_group 0;" ::: "memory");
        }
        __syncthreads();

        const uint32_t stA = aBase + (i & 3) * STAGE;
        const uint32_t stB = bBase + (i & 3) * STAGE;

        // Batch ALL ldmatrix for both ks-steps; ks=1 loads complete under
        // the shadow of ks=0 MMAs.
        uint32_t ah[2][2][4], bh[2][4][4];
        #pragma unroll
        for (int ks = 0; ks < 2; ks++) {
            #pragma unroll
            for (int mf = 0; mf < 2; mf++)
                LDMX4(ah[ks][mf], stA + mf * (16 * ROWB) + ks * 32);
            #pragma unroll
            for (int ng = 0; ng < 4; ng++)
                LDMX4(bh[ks][ng], stB + ng * (16 * ROWB) + ks * 32);
        }
        #pragma unroll
        for (int ks = 0; ks < 2; ks++)
            #pragma unroll
            for (int ng = 0; ng < 4; ng++)
                #pragma unroll
                for (int mf = 0; mf < 2; mf++) {
                    MMA_F16(acc[mf][ng * 2 + 0], ah[ks][mf],
                            bh[ks][ng][0], bh[ks][ng][2]);
                    MMA_F16(acc[mf][ng * 2 + 1], ah[ks][mf],
                            bh[ks][ng][1], bh[ks][ng][3]);
                }
    }
#undef LOADSTAGE

    // ---- epilogue
    const long baseM = (long)blockIdx.y * 128 + warp_m * 32;
    const long baseN = (long)blockIdx.x * 128 + warp_n * 64;
    const int rq = lane >> 2;
    const int cq = (lane & 3) * 2;
    #pragma unroll
    for (int mf = 0; mf < 2; mf++) {
        #pragma unroll
        for (int nf = 0; nf < 8; nf++) {
            const long r0 = baseM + mf * 16 + rq;
            const long c0 = baseN + nf * 8 + cq;
            float v0 = acc[mf][nf][0] * alpha;
            float v1 = acc[mf][nf][1] * alpha;
            float v2 = acc[mf][nf][2] * alpha;
            float v3 = acc[mf][nf][3] * alpha;
            if (mode == 0) {
                float* o0 = Cf + z * sC + r0 * ldC + c0;
                *(float2*)o0 = make_float2(v0, v1);
                *(float2*)(o0 + 8 * ldC) = make_float2(v2, v3);
            } else {
                __half* oh0 = Ch + z * sC + r0 * ldC + c0;
                *(__half2*)oh0 = __halves2half2(__float2half_rn(v0),
                                                __float2half_rn(v1));
                *(__half2*)(oh0 + 8 * ldC) = __halves2half2(__float2half_rn(v2),
                                                            __float2half_rn(v3));
            }
        }
    }
}

// ---------------------------------------------------------------------------
// Fused prep: X fp32->fp16 convert + 4 weight transposes, one launch.
// ---------------------------------------------------------------------------
__global__ __launch_bounds__(256)
void prep(const float* __restrict__ X,
          const float* __restrict__ WQ, const float* __restrict__ WK,
          const float* __restrict__ WV, const float* __restrict__ WO,
          __half* __restrict__ Xh, __half* __restrict__ Wqkvt,
          __half* __restrict__ WOt)
{
    __shared__ float t[32][33];
    const int bid = blockIdx.x;
    const int tid = threadIdx.x;

    if (bid < 8192) {
        int i = bid * 256 + tid;
        float4 v = ((const float4*)X)[i];
        ((__half2*)Xh)[2 * i]     = __halves2half2(__float2half_rn(v.x),
                                                   __float2half_rn(v.y));
        ((__half2*)Xh)[2 * i + 1] = __halves2half2(__float2half_rn(v.z),
                                                   __float2half_rn(v.w));
        return;
    }

    const int wb = bid - 8192;
    const int wi = wb >> 10;
    const int b  = wb & 1023;
    const float* src = (wi == 0) ? WQ : (wi == 1) ? WK : (wi == 2) ? WV : WO;
    __half* dst = (wi == 3) ? WOt : (Wqkvt + (long)wi * D_ * D_);

    const int c0 = (b & 31) * 32, r0 = (b >> 5) * 32;
    const int tx = tid & 31, ty = tid >> 5;
    #pragma unroll
    for (int j = 0; j < 4; j++)
        t[ty + 8 * j][tx] = src[(long)(r0 + ty + 8 * j) * D_ + c0 + tx];
    __syncthreads();
    #pragma unroll
    for (int j = 0; j < 4; j++)
        dst[(long)(c0 + ty + 8 * j) * D_ + r0 + tx] =
            __float2half_rn(t[tx][ty + 8 * j]);
}

// ---------------------------------------------------------------------------
// fp16 strided [R,C] (row stride ldIn) -> transposed fp16 [C,R] (batched)
// ---------------------------------------------------------------------------
__global__ void tr16(const __half* __restrict__ in,
                     __half* __restrict__ out,
                     int R, int C, long ldIn, long sIn, long sOut)
{
    __shared__ __half t[32][34];
    const __half* ip = in + (long)blockIdx.z * sIn;
    const int c0 = blockIdx.x * 32, r0 = blockIdx.y * 32;
    const int tx = threadIdx.x, ty = threadIdx.y;
    #pragma unroll
    for (int j = 0; j < 4; j++)
        t[ty + 8 * j][tx] = ip[(long)(r0 + ty + 8 * j) * ldIn + c0 + tx];
    __syncthreads();
    __half* op = out + (long)blockIdx.z * sOut;
    #pragma unroll
    for (int j = 0; j < 4; j++)
        op[(long)(c0 + ty + 8 * j) * R + r0 + tx] = t[tx][ty + 8 * j];
}

// ---------------------------------------------------------------------------
// Row softmax over length-2048 rows; fp32 in, fp16 out. float4 loads.
// ---------------------------------------------------------------------------
__global__ __launch_bounds__(256)
void softmax_rows(const float* __restrict__ S, __half* __restrict__ P)
{
    const long base = (long)blockIdx.x * S_;
    const float4* row4 = (const float4*)(S + base);
    const int tid  = threadIdx.x;
    const int lane = tid & 31;
    const int warp = tid >> 5;
    __shared__ float red[8];

    float4 va = row4[tid];
    float4 vb = row4[tid + 256];
    float m = fmaxf(fmaxf(fmaxf(va.x, va.y), fmaxf(va.z, va.w)),
                    fmaxf(fmaxf(vb.x, vb.y), fmaxf(vb.z, vb.w)));
    #pragma unroll
    for (int o = 16; o > 0; o >>= 1) m = fmaxf(m, __shfl_xor_sync(0xffffffffu, m, o));
    if (lane == 0) red[warp] = m;
    __syncthreads();
    m = red[lane & 7];
    #pragma unroll
    for (int o = 4; o > 0; o >>= 1) m = fmaxf(m, __shfl_xor_sync(0xffffffffu, m, o));
    m = __shfl_sync(0xffffffffu, m, 0);

    va.x = __expf(va.x - m); va.y = __expf(va.y - m);
    va.z = __expf(va.z - m); va.w = __expf(va.w - m);
    vb.x = __expf(vb.x - m); vb.y = __expf(vb.y - m);
    vb.z = __expf(vb.z - m); vb.w = __expf(vb.w - m);
    float s = va.x + va.y + va.z + va.w + vb.x + vb.y + vb.z + vb.w;
    #pragma unroll
    for (int o = 16; o > 0; o >>= 1) s += __shfl_xor_sync(0xffffffffu, s, o);
    __syncthreads();
    if (lane == 0) red[warp] = s;
    __syncthreads();
    s = red[lane & 7];
    #pragma unroll
    for (int o = 4; o > 0; o >>= 1) s += __shfl_xor_sync(0xffffffffu, s, o);
    s = __shfl_sync(0xffffffffu, s, 0);

    const float inv = 1.f / s;
    __half2* p2 = (__half2*)(P + base);
    p2[2 * tid]       = __halves2half2(__float2half_rn(va.x * inv),
                                       __float2half_rn(va.y * inv));
    p2[2 * tid + 1]   = __halves2half2(__float2half_rn(va.z * inv),
                                       __float2half_rn(va.w * inv));
    p2[2 * (tid+256)]     = __halves2half2(__float2half_rn(vb.x * inv),
                                           __float2half_rn(vb.y * inv));
    p2[2 * (tid+256) + 1] = __halves2half2(__float2half_rn(vb.z * inv),
                                           __float2half_rn(vb.w * inv));
}

// ---------------------------------------------------------------------------
extern "C" void kernel_launch(void* const* d_in, const int* in_sizes, int n_in,
                              void* d_out, int out_size)
{
    const float* X  = (const float*)d_in[0];
    const float* WQ = (const float*)d_in[1];
    const float* WK = (const float*)d_in[2];
    const float* WV = (const float*)d_in[3];
    const float* WO = (const float*)d_in[4];
    float* Y = (float*)d_out;

    __half *Xh, *Wqkvt, *WOt, *QKV, *Vth, *Ph, *Hh;
    float *Sc;
    cudaGetSymbolAddress((void**)&Xh,    g_Xh);
    cudaGetSymbolAddress((void**)&Wqkvt, g_Wqkvt);
    cudaGetSymbolAddress((void**)&WOt,   g_WOt);
    cudaGetSymbolAddress((void**)&QKV,   g_QKV);
    cudaGetSymbolAddress((void**)&Vth,   g_Vth);
    cudaGetSymbolAddress((void**)&Sc,    g_Sc);
    cudaGetSymbolAddress((void**)&Ph,    g_Ph);
    cudaGetSymbolAddress((void**)&Hh,    g_Hh);

    cudaFuncSetAttribute(gemmh, cudaFuncAttributeMaxDynamicSharedMemorySize,
                         GEMM_SMEM);

    dim3 thr(256);
    dim3 tW(32, 8);
    const long LD3 = 3 * D_;                  // 3072

    // Fused input conversions (X convert + 4 W transposes)
    prep<<<8192 + 4096, thr>>>(X, WQ, WK, WV, WO, Xh, Wqkvt, WOt);

    // Fused QKV projection: [8192, 3072] = Xh · Wqkvt^T, fp16 out
    gemmh<<<dim3(24, 64, 1), thr, GEMM_SMEM>>>(Xh, Wqkvt, nullptr, QKV,
                                               D_, D_, D_, LD3,
                                               0, 0, 0, 1.f, 2);

    // V slice -> per-batch transpose [1024, 2048] fp16
    tr16<<<dim3(D_ / 32, S_ / 32, B_), tW>>>(QKV + 2 * D_, Vth,
                                             S_, D_, LD3,
                                             (long)S_ * LD3, (long)S_ * D_);

    // Scores: per-batch [2048,2048] = Q · K^T / 32 -> fp32
    gemmh<<<dim3(16, 16, 4), thr, GEMM_SMEM>>>(QKV, QKV + D_, Sc, nullptr,
                                               D_, LD3, LD3, S_,
                                               (long)S_ * LD3, (long)S_ * LD3,
                                               (long)S_ * S_, 1.f / 32.f, 0);

    // Softmax -> probs fp16
    softmax_rows<<<B_ * S_, thr>>>(Sc, Ph);

    // H = P · V^T : per-batch [2048,1024], fp16 out
    gemmh<<<dim3(8, 16, 4), thr, GEMM_SMEM>>>(Ph, Vth, nullptr, Hh,
                                              S_, S_, S_, D_,
                                              (long)S_ * S_, (long)S_ * D_,
                                              (long)S_ * D_, 1.f, 2);

    // Output: [8192,1024] = Hh · WOt^T -> fp32 to d_out
    gemmh<<<dim3(8, 64, 1), thr, GEMM_SMEM>>>(Hh, WOt, Y, nullptr,
                                              D_, D_, D_, D_,
                                              0, 0, 0, 1.f, 0);
}

// round 16
// speedup vs baseline: 1.1407x; 1.0024x over previous
#include <cuda_runtime.h>
#include <cuda_fp16.h>
#include <math.h>
#include <stdint.h>

// ---------------------------------------------------------------------------
// Problem constants
// ---------------------------------------------------------------------------
#define B_  4
#define S_  2048
#define D_  1024
#define M_TOK (B_ * S_)            // 8192

// ---------------------------------------------------------------------------
// Scratch (device globals; allocation in kernel_launch is forbidden)
// ---------------------------------------------------------------------------
__device__ __half g_Xh   [M_TOK * D_];
__device__ __half g_Wqkvt[3 * D_ * D_];      // [3072 N-rows, 1024 K]
__device__ __half g_WOt  [D_ * D_];
__device__ __half g_QKV  [(long)M_TOK * 3 * D_];  // [8192, 3072] fp16
__device__ __half g_Vth  [M_TOK * D_];       // per-batch [1024, 2048]
__device__ __half g_Sch  [(long)B_ * S_ * S_];    // fp16 scaled logits
__device__ __half g_Ph   [(long)B_ * S_ * S_];
__device__ __half g_Hh   [M_TOK * D_];

// ---------------------------------------------------------------------------
// Helpers
// ---------------------------------------------------------------------------
__device__ __forceinline__ uint32_t smem_u32(const void* p) {
    uint32_t a;
    asm("{ .reg .u64 t; cvta.to.shared.u64 t, %1; cvt.u32.u64 %0, t; }"
        : "=r"(a) : "l"(p));
    return a;
}

#define CP16(dst, src) \
    asm volatile("cp.async.cg.shared.global [%0], [%1], 16;" \
                 :: "r"((uint32_t)(dst)), "l"(src))

#define LDMX4(r, addr) \
    asm volatile("ldmatrix.sync.aligned.m8n8.x4.shared.b16 {%0,%1,%2,%3}, [%4];" \
                 : "=r"((r)[0]), "=r"((r)[1]), "=r"((r)[2]), "=r"((r)[3]) \
                 : "r"(addr))

#define MMA_F16(d, a, b0, b1) \
    asm("mma.sync.aligned.m16n8k16.row.col.f32.f16.f16.f32 " \
        "{%0,%1,%2,%3}, {%4,%5,%6,%7}, {%8,%9}, {%0,%1,%2,%3};" \
        : "+f"((d)[0]), "+f"((d)[1]), "+f"((d)[2]), "+f"((d)[3]) \
        : "r"((a)[0]), "r"((a)[1]), "r"((a)[2]), "r"((a)[3]), \
          "r"(b0), "r"(b1))

// ---------------------------------------------------------------------------
// fp16 mma.sync GEMM:  C[M,N] = alpha * A[M,K] · B[N,K]^T
// CTA tile 128x128, BK=32, 256 thr (8 warps as 4m x 2n, warp tile 32x64).
// cp.async 4-stage pipeline, ONE __syncthreads per K-iter, 80B row pitch,
// ALL ldmatrix of both ks-steps batched before the MMAs, 2 CTAs/SM.
// Measured optimum across 6 mainloop variants; saturates the legacy
// mma.sync issue ceiling (~49% of rated tensor pipe) on this part.
// mode 0: fp32 C (row stride ldC).  mode 2: fp16 C (row stride ldC).
// Batched via blockIdx.z (element strides sA/sB/sC).
// ---------------------------------------------------------------------------
#define ROWB 80
#define TROWS 256
#define STAGE (TROWS * ROWB)                 // 20480
#define OFFB  (128 * ROWB)
#define GEMM_SMEM (4 * STAGE)                // 81920

__global__ __launch_bounds__(256, 2)
void gemmh(const __half* __restrict__ A, const __half* __restrict__ B,
           float* __restrict__ Cf, __half* __restrict__ Ch,
           int K, long ldA, long ldB, long ldC,
           long sA, long sB, long sC, float alpha, int mode)
{
    extern __shared__ char smem[];
    const uint32_t sb = smem_u32(smem);
    const int tid  = threadIdx.x;
    const int wid  = tid >> 5;
    const int lane = tid & 31;
    const long z   = blockIdx.z;

    // ---- global->smem load geometry: 256 rows * 64B of K; 4 chunks/thread
    const long rowA = (long)blockIdx.y * 128;
    const long rowB = (long)blockIdx.x * 128;
    const char* gp[4];
    uint32_t sw[4];
    #pragma unroll
    for (int j = 0; j < 4; j++) {
        int c = tid + 256 * j;
        int r = c >> 2;
        int col = (c & 3) * 16;
        sw[j] = (uint32_t)(r * ROWB + col);
        if (r < 128)
            gp[j] = (const char*)(A + z * sA + (rowA + r) * ldA) + col;
        else
            gp[j] = (const char*)(B + z * sB + (rowB + r - 128) * ldB) + col;
    }

    // ---- ldmatrix geometry: warp tile 32x64 (4m x 2n warps)
    const int warp_m = wid & 3;
    const int warp_n = wid >> 2;
    const int quad = lane >> 3;
    const int lr8  = lane & 7;
    const uint32_t aBase = sb + (uint32_t)((warp_m * 32 + lr8 + (quad & 1) * 8) * ROWB
                                           + (quad >> 1) * 16);
    const uint32_t bBase = sb + OFFB + (uint32_t)((warp_n * 64 + lr8 + (quad & 1) * 8) * ROWB
                                                  + (quad >> 1) * 16);

    float acc[2][8][4];
    #pragma unroll
    for (int mf = 0; mf < 2; mf++)
        #pragma unroll
        for (int nf = 0; nf < 8; nf++)
            #pragma unroll
            for (int q = 0; q < 4; q++) acc[mf][nf][q] = 0.f;

    const int nc = K >> 5;

#define LOADSTAGE(base, ko) do { \
    _Pragma("unroll") \
    for (int j = 0; j < 4; j++) CP16((base) + sw[j], gp[j] + (ko)); \
    asm volatile("cp.async.commit_group;" ::: "memory"); \
} while (0)

    LOADSTAGE(sb, 0);
    LOADSTAGE(sb + STAGE, 64);

    for (int i = 0; i < nc; i++) {
        if (i + 2 < nc) {
            LOADSTAGE(sb + ((i + 2) & 3) * STAGE, (long)(i + 2) * 64);
            asm volatile("cp.async.wait_group 2;" ::: "memory");
        } else if (i + 1 < nc) {
            asm volatile("cp.async.wait_group 1;" ::: "memory");
        } else {
            asm volatile("cp.async.wait_group 0;" ::: "memory");
        }
        __syncthreads();

        const uint32_t stA = aBase + (i & 3) * STAGE;
        const uint32_t stB = bBase + (i & 3) * STAGE;

        // Batch ALL ldmatrix for both ks-steps; ks=1 loads complete under
        // the shadow of ks=0 MMAs.
        uint32_t ah[2][2][4], bh[2][4][4];
        #pragma unroll
        for (int ks = 0; ks < 2; ks++) {
            #pragma unroll
            for (int mf = 0; mf < 2; mf++)
                LDMX4(ah[ks][mf], stA + mf * (16 * ROWB) + ks * 32);
            #pragma unroll
            for (int ng = 0; ng < 4; ng++)
                LDMX4(bh[ks][ng], stB + ng * (16 * ROWB) + ks * 32);
        }
        #pragma unroll
        for (int ks = 0; ks < 2; ks++)
            #pragma unroll
            for (int ng = 0; ng < 4; ng++)
                #pragma unroll
                for (int mf = 0; mf < 2; mf++) {
                    MMA_F16(acc[mf][ng * 2 + 0], ah[ks][mf],
                            bh[ks][ng][0], bh[ks][ng][2]);
                    MMA_F16(acc[mf][ng * 2 + 1], ah[ks][mf],
                            bh[ks][ng][1], bh[ks][ng][3]);
                }
    }
#undef LOADSTAGE

    // ---- epilogue
    const long baseM = (long)blockIdx.y * 128 + warp_m * 32;
    const long baseN = (long)blockIdx.x * 128 + warp_n * 64;
    const int rq = lane >> 2;
    const int cq = (lane & 3) * 2;
    #pragma unroll
    for (int mf = 0; mf < 2; mf++) {
        #pragma unroll
        for (int nf = 0; nf < 8; nf++) {
            const long r0 = baseM + mf * 16 + rq;
            const long c0 = baseN + nf * 8 + cq;
            float v0 = acc[mf][nf][0] * alpha;
            float v1 = acc[mf][nf][1] * alpha;
            float v2 = acc[mf][nf][2] * alpha;
            float v3 = acc[mf][nf][3] * alpha;
            if (mode == 0) {
                float* o0 = Cf + z * sC + r0 * ldC + c0;
                *(float2*)o0 = make_float2(v0, v1);
                *(float2*)(o0 + 8 * ldC) = make_float2(v2, v3);
            } else {
                __half* oh0 = Ch + z * sC + r0 * ldC + c0;
                *(__half2*)oh0 = __halves2half2(__float2half_rn(v0),
                                                __float2half_rn(v1));
                *(__half2*)(oh0 + 8 * ldC) = __halves2half2(__float2half_rn(v2),
                                                            __float2half_rn(v3));
            }
        }
    }
}

// ---------------------------------------------------------------------------
// Fused prep: X fp32->fp16 convert + 4 weight transposes, one launch.
// ---------------------------------------------------------------------------
__global__ __launch_bounds__(256)
void prep(const float* __restrict__ X,
          const float* __restrict__ WQ, const float* __restrict__ WK,
          const float* __restrict__ WV, const float* __restrict__ WO,
          __half* __restrict__ Xh, __half* __restrict__ Wqkvt,
          __half* __restrict__ WOt)
{
    __shared__ float t[32][33];
    const int bid = blockIdx.x;
    const int tid = threadIdx.x;

    if (bid < 8192) {
        int i = bid * 256 + tid;
        float4 v = ((const float4*)X)[i];
        ((__half2*)Xh)[2 * i]     = __halves2half2(__float2half_rn(v.x),
                                                   __float2half_rn(v.y));
        ((__half2*)Xh)[2 * i + 1] = __halves2half2(__float2half_rn(v.z),
                                                   __float2half_rn(v.w));
        return;
    }

    const int wb = bid - 8192;
    const int wi = wb >> 10;
    const int b  = wb & 1023;
    const float* src = (wi == 0) ? WQ : (wi == 1) ? WK : (wi == 2) ? WV : WO;
    __half* dst = (wi == 3) ? WOt : (Wqkvt + (long)wi * D_ * D_);

    const int c0 = (b & 31) * 32, r0 = (b >> 5) * 32;
    const int tx = tid & 31, ty = tid >> 5;
    #pragma unroll
    for (int j = 0; j < 4; j++)
        t[ty + 8 * j][tx] = src[(long)(r0 + ty + 8 * j) * D_ + c0 + tx];
    __syncthreads();
    #pragma unroll
    for (int j = 0; j < 4; j++)
        dst[(long)(c0 + ty + 8 * j) * D_ + r0 + tx] =
            __float2half_rn(t[tx][ty + 8 * j]);
}

// ---------------------------------------------------------------------------
// fp16 strided [R,C] (row stride ldIn) -> transposed fp16 [C,R] (batched)
// ---------------------------------------------------------------------------
__global__ void tr16(const __half* __restrict__ in,
                     __half* __restrict__ out,
                     int R, int C, long ldIn, long sIn, long sOut)
{
    __shared__ __half t[32][34];
    const __half* ip = in + (long)blockIdx.z * sIn;
    const int c0 = blockIdx.x * 32, r0 = blockIdx.y * 32;
    const int tx = threadIdx.x, ty = threadIdx.y;
    #pragma unroll
    for (int j = 0; j < 4; j++)
        t[ty + 8 * j][tx] = ip[(long)(r0 + ty + 8 * j) * ldIn + c0 + tx];
    __syncthreads();
    __half* op = out + (long)blockIdx.z * sOut;
    #pragma unroll
    for (int j = 0; j < 4; j++)
        op[(long)(c0 + ty + 8 * j) * R + r0 + tx] = t[tx][ty + 8 * j];
}

// ---------------------------------------------------------------------------
// Row softmax over length-2048 rows; fp16 in (scaled logits), fp16 out.
// ---------------------------------------------------------------------------
__global__ __launch_bounds__(256)
void softmax_rows(const __half* __restrict__ Sh, __half* __restrict__ P)
{
    const long base = (long)blockIdx.x * S_;
    const uint2* row2 = (const uint2*)(Sh + base);   // 4 halves per uint2
    const int tid  = threadIdx.x;
    const int lane = tid & 31;
    const int warp = tid >> 5;
    __shared__ float red[8];

    uint2 ua = row2[tid];
    uint2 ub = row2[tid + 256];
    float2 a0 = __half22float2(*(const __half2*)&ua.x);
    float2 a1 = __half22float2(*(const __half2*)&ua.y);
    float2 b0 = __half22float2(*(const __half2*)&ub.x);
    float2 b1 = __half22float2(*(const __half2*)&ub.y);

    float m = fmaxf(fmaxf(fmaxf(a0.x, a0.y), fmaxf(a1.x, a1.y)),
                    fmaxf(fmaxf(b0.x, b0.y), fmaxf(b1.x, b1.y)));
    #pragma unroll
    for (int o = 16; o > 0; o >>= 1) m = fmaxf(m, __shfl_xor_sync(0xffffffffu, m, o));
    if (lane == 0) red[warp] = m;
    __syncthreads();
    m = red[lane & 7];
    #pragma unroll
    for (int o = 4; o > 0; o >>= 1) m = fmaxf(m, __shfl_xor_sync(0xffffffffu, m, o));
    m = __shfl_sync(0xffffffffu, m, 0);

    a0.x = __expf(a0.x - m); a0.y = __expf(a0.y - m);
    a1.x = __expf(a1.x - m); a1.y = __expf(a1.y - m);
    b0.x = __expf(b0.x - m); b0.y = __expf(b0.y - m);
    b1.x = __expf(b1.x - m); b1.y = __expf(b1.y - m);
    float s = a0.x + a0.y + a1.x + a1.y + b0.x + b0.y + b1.x + b1.y;
    #pragma unroll
    for (int o = 16; o > 0; o >>= 1) s += __shfl_xor_sync(0xffffffffu, s, o);
    __syncthreads();
    if (lane == 0) red[warp] = s;
    __syncthreads();
    s = red[lane & 7];
    #pragma unroll
    for (int o = 4; o > 0; o >>= 1) s += __shfl_xor_sync(0xffffffffu, s, o);
    s = __shfl_sync(0xffffffffu, s, 0);

    const float inv = 1.f / s;
    __half2* p2 = (__half2*)(P + base);
    p2[2 * tid]       = __halves2half2(__float2half_rn(a0.x * inv),
                                       __float2half_rn(a0.y * inv));
    p2[2 * tid + 1]   = __halves2half2(__float2half_rn(a1.x * inv),
                                       __float2half_rn(a1.y * inv));
    p2[2 * (tid+256)]     = __halves2half2(__float2half_rn(b0.x * inv),
                                           __float2half_rn(b0.y * inv));
    p2[2 * (tid+256) + 1] = __halves2half2(__float2half_rn(b1.x * inv),
                                           __float2half_rn(b1.y * inv));
}

// ---------------------------------------------------------------------------
extern "C" void kernel_launch(void* const* d_in, const int* in_sizes, int n_in,
                              void* d_out, int out_size)
{
    const float* X  = (const float*)d_in[0];
    const float* WQ = (const float*)d_in[1];
    const float* WK = (const float*)d_in[2];
    const float* WV = (const float*)d_in[3];
    const float* WO = (const float*)d_in[4];
    float* Y = (float*)d_out;

    __half *Xh, *Wqkvt, *WOt, *QKV, *Vth, *Sch, *Ph, *Hh;
    cudaGetSymbolAddress((void**)&Xh,    g_Xh);
    cudaGetSymbolAddress((void**)&Wqkvt, g_Wqkvt);
    cudaGetSymbolAddress((void**)&WOt,   g_WOt);
    cudaGetSymbolAddress((void**)&QKV,   g_QKV);
    cudaGetSymbolAddress((void**)&Vth,   g_Vth);
    cudaGetSymbolAddress((void**)&Sch,   g_Sch);
    cudaGetSymbolAddress((void**)&Ph,    g_Ph);
    cudaGetSymbolAddress((void**)&Hh,    g_Hh);

    cudaFuncSetAttribute(gemmh, cudaFuncAttributeMaxDynamicSharedMemorySize,
                         GEMM_SMEM);

    dim3 thr(256);
    dim3 tW(32, 8);
    const long LD3 = 3 * D_;                  // 3072

    // Fused input conversions (X convert + 4 W transposes)
    prep<<<8192 + 4096, thr>>>(X, WQ, WK, WV, WO, Xh, Wqkvt, WOt);

    // Fused QKV projection: [8192, 3072] = Xh · Wqkvt^T, fp16 out
    gemmh<<<dim3(24, 64, 1), thr, GEMM_SMEM>>>(Xh, Wqkvt, nullptr, QKV,
                                               D_, D_, D_, LD3,
                                               0, 0, 0, 1.f, 2);

    // V slice -> per-batch transpose [1024, 2048] fp16
    tr16<<<dim3(D_ / 32, S_ / 32, B_), tW>>>(QKV + 2 * D_, Vth,
                                             S_, D_, LD3,
                                             (long)S_ * LD3, (long)S_ * D_);

    // Scores: per-batch [2048,2048] = Q · K^T / 32 -> fp16 (scale folded
    // before rounding; logit rounding adds ~5e-4 RMS, inside budget)
    gemmh<<<dim3(16, 16, 4), thr, GEMM_SMEM>>>(QKV, QKV + D_, nullptr, Sch,
                                               D_, LD3, LD3, S_,
                                               (long)S_ * LD3, (long)S_ * LD3,
                                               (long)S_ * S_, 1.f / 32.f, 2);

    // Softmax (fp16 in) -> probs fp16
    softmax_rows<<<B_ * S_, thr>>>(Sch, Ph);

    // H = P · V^T : per-batch [2048,1024], fp16 out
    gemmh<<<dim3(8, 16, 4), thr, GEMM_SMEM>>>(Ph, Vth, nullptr, Hh,
                                              S_, S_, S_, D_,
                                              (long)S_ * S_, (long)S_ * D_,
                                              (long)S_ * D_, 1.f, 2);

    // Output: [8192,1024] = Hh · WOt^T -> fp32 to d_out
    gemmh<<<dim3(8, 64, 1), thr, GEMM_SMEM>>>(Hh, WOt, Y, nullptr,
                                              D_, D_, D_, D_,
                                              0, 0, 0, 1.f, 0);
}

// round 17
// speedup vs baseline: 1.1784x; 1.0330x over previous
#include <cuda_runtime.h>
#include <cuda_fp16.h>
#include <math.h>
#include <stdint.h>

// ---------------------------------------------------------------------------
// Problem constants
// ---------------------------------------------------------------------------
#define B_  4
#define S_  2048
#define D_  1024
#define M_TOK (B_ * S_)            // 8192

// ---------------------------------------------------------------------------
// Scratch (device globals; allocation in kernel_launch is forbidden)
// ---------------------------------------------------------------------------
__device__ __half g_Xh   [M_TOK * D_];
__device__ __half g_Wqkvt[3 * D_ * D_];      // [3072 N-rows, 1024 K]
__device__ __half g_WOt  [D_ * D_];
__device__ __half g_QKV  [(long)M_TOK * 3 * D_];  // [8192, 3072] fp16
__device__ __half g_Sch  [(long)B_ * S_ * S_];    // fp16 scaled logits
__device__ __half g_Ph   [(long)B_ * S_ * S_];
__device__ __half g_Hh   [M_TOK * D_];

// ---------------------------------------------------------------------------
// Helpers
// ---------------------------------------------------------------------------
__device__ __forceinline__ uint32_t smem_u32(const void* p) {
    uint32_t a;
    asm("{ .reg .u64 t; cvta.to.shared.u64 t, %1; cvt.u32.u64 %0, t; }"
        : "=r"(a) : "l"(p));
    return a;
}

#define CP16(dst, src) \
    asm volatile("cp.async.cg.shared.global [%0], [%1], 16;" \
                 :: "r"((uint32_t)(dst)), "l"(src))

#define LDMX4(r, addr) \
    asm volatile("ldmatrix.sync.aligned.m8n8.x4.shared.b16 {%0,%1,%2,%3}, [%4];" \
                 : "=r"((r)[0]), "=r"((r)[1]), "=r"((r)[2]), "=r"((r)[3]) \
                 : "r"(addr))

#define LDMX4T(r, addr) \
    asm volatile("ldmatrix.sync.aligned.m8n8.x4.trans.shared.b16 {%0,%1,%2,%3}, [%4];" \
                 : "=r"((r)[0]), "=r"((r)[1]), "=r"((r)[2]), "=r"((r)[3]) \
                 : "r"(addr))

#define MMA_F16(d, a, b0, b1) \
    asm("mma.sync.aligned.m16n8k16.row.col.f32.f16.f16.f32 " \
        "{%0,%1,%2,%3}, {%4,%5,%6,%7}, {%8,%9}, {%0,%1,%2,%3};" \
        : "+f"((d)[0]), "+f"((d)[1]), "+f"((d)[2]), "+f"((d)[3]) \
        : "r"((a)[0]), "r"((a)[1]), "r"((a)[2]), "r"((a)[3]), \
          "r"(b0), "r"(b1))

// ---------------------------------------------------------------------------
// gemmh: C[M,N] = alpha * A[M,K] · B[N,K]^T  (B K-major). Proven optimum:
// CTA 128x128, BK=32, 256 thr (4m x 2n warps, warp tile 32x64), 4-stage
// cp.async, one sync/iter, 80B pitch, batched ldsm, 2 CTAs/SM.
// mode 0: fp32 C.  mode 2: fp16 C.  Batched via blockIdx.z.
// ---------------------------------------------------------------------------
#define ROWB 80
#define TROWS 256
#define STAGE (TROWS * ROWB)                 // 20480
#define OFFB  (128 * ROWB)
#define GEMM_SMEM (4 * STAGE)                // 81920

__global__ __launch_bounds__(256, 2)
void gemmh(const __half* __restrict__ A, const __half* __restrict__ B,
           float* __restrict__ Cf, __half* __restrict__ Ch,
           int K, long ldA, long ldB, long ldC,
           long sA, long sB, long sC, float alpha, int mode)
{
    extern __shared__ char smem[];
    const uint32_t sb = smem_u32(smem);
    const int tid  = threadIdx.x;
    const int wid  = tid >> 5;
    const int lane = tid & 31;
    const long z   = blockIdx.z;

    const long rowA = (long)blockIdx.y * 128;
    const long rowB = (long)blockIdx.x * 128;
    const char* gp[4];
    uint32_t sw[4];
    #pragma unroll
    for (int j = 0; j < 4; j++) {
        int c = tid + 256 * j;
        int r = c >> 2;
        int col = (c & 3) * 16;
        sw[j] = (uint32_t)(r * ROWB + col);
        if (r < 128)
            gp[j] = (const char*)(A + z * sA + (rowA + r) * ldA) + col;
        else
            gp[j] = (const char*)(B + z * sB + (rowB + r - 128) * ldB) + col;
    }

    const int warp_m = wid & 3;
    const int warp_n = wid >> 2;
    const int quad = lane >> 3;
    const int lr8  = lane & 7;
    const uint32_t aBase = sb + (uint32_t)((warp_m * 32 + lr8 + (quad & 1) * 8) * ROWB
                                           + (quad >> 1) * 16);
    const uint32_t bBase = sb + OFFB + (uint32_t)((warp_n * 64 + lr8 + (quad & 1) * 8) * ROWB
                                                  + (quad >> 1) * 16);

    float acc[2][8][4];
    #pragma unroll
    for (int mf = 0; mf < 2; mf++)
        #pragma unroll
        for (int nf = 0; nf < 8; nf++)
            #pragma unroll
            for (int q = 0; q < 4; q++) acc[mf][nf][q] = 0.f;

    const int nc = K >> 5;

#define LOADSTAGE(base, ko) do { \
    _Pragma("unroll") \
    for (int j = 0; j < 4; j++) CP16((base) + sw[j], gp[j] + (ko)); \
    asm volatile("cp.async.commit_group;" ::: "memory"); \
} while (0)

    LOADSTAGE(sb, 0);
    LOADSTAGE(sb + STAGE, 64);

    for (int i = 0; i < nc; i++) {
        if (i + 2 < nc) {
            LOADSTAGE(sb + ((i + 2) & 3) * STAGE, (long)(i + 2) * 64);
            asm volatile("cp.async.wait_group 2;" ::: "memory");
        } else if (i + 1 < nc) {
            asm volatile("cp.async.wait_group 1;" ::: "memory");
        } else {
            asm volatile("cp.async.wait_group 0;" ::: "memory");
        }
        __syncthreads();

        const uint32_t stA = aBase + (i & 3) * STAGE;
        const uint32_t stB = bBase + (i & 3) * STAGE;

        uint32_t ah[2][2][4], bh[2][4][4];
        #pragma unroll
        for (int ks = 0; ks < 2; ks++) {
            #pragma unroll
            for (int mf = 0; mf < 2; mf++)
                LDMX4(ah[ks][mf], stA + mf * (16 * ROWB) + ks * 32);
            #pragma unroll
            for (int ng = 0; ng < 4; ng++)
                LDMX4(bh[ks][ng], stB + ng * (16 * ROWB) + ks * 32);
        }
        #pragma unroll
        for (int ks = 0; ks < 2; ks++)
            #pragma unroll
            for (int ng = 0; ng < 4; ng++)
                #pragma unroll
                for (int mf = 0; mf < 2; mf++) {
                    MMA_F16(acc[mf][ng * 2 + 0], ah[ks][mf],
                            bh[ks][ng][0], bh[ks][ng][2]);
                    MMA_F16(acc[mf][ng * 2 + 1], ah[ks][mf],
                            bh[ks][ng][1], bh[ks][ng][3]);
                }
    }
#undef LOADSTAGE

    const long baseM = (long)blockIdx.y * 128 + warp_m * 32;
    const long baseN = (long)blockIdx.x * 128 + warp_n * 64;
    const int rq = lane >> 2;
    const int cq = (lane & 3) * 2;
    #pragma unroll
    for (int mf = 0; mf < 2; mf++) {
        #pragma unroll
        for (int nf = 0; nf < 8; nf++) {
            const long r0 = baseM + mf * 16 + rq;
            const long c0 = baseN + nf * 8 + cq;
            float v0 = acc[mf][nf][0] * alpha;
            float v1 = acc[mf][nf][1] * alpha;
            float v2 = acc[mf][nf][2] * alpha;
            float v3 = acc[mf][nf][3] * alpha;
            if (mode == 0) {
                float* o0 = Cf + z * sC + r0 * ldC + c0;
                *(float2*)o0 = make_float2(v0, v1);
                *(float2*)(o0 + 8 * ldC) = make_float2(v2, v3);
            } else {
                __half* oh0 = Ch + z * sC + r0 * ldC + c0;
                *(__half2*)oh0 = __halves2half2(__float2half_rn(v0),
                                                __float2half_rn(v1));
                *(__half2*)(oh0 + 8 * ldC) = __halves2half2(__float2half_rn(v2),
                                                            __float2half_rn(v3));
            }
        }
    }
}

// ---------------------------------------------------------------------------
// gemmt: C[M,N] = A[M,K] · Bv[K,N]  (B row-major [K,N] — e.g. V in-place).
// B fragments built with ldmatrix.x4.trans from [k-rows, n-cols] smem tile
// (pitch 272B: trans reads conflict-free). Same mainloop/occupancy as gemmh.
// fp16 C out. Batched via blockIdx.z.
// ---------------------------------------------------------------------------
#define BPITCH 272
#define TOFFB  (128 * ROWB)                  // 10240 (A tile first)
#define TSTAGE (TOFFB + 32 * BPITCH)         // 18944
#define GEMMT_SMEM (4 * TSTAGE)              // 75776

__global__ __launch_bounds__(256, 2)
void gemmt(const __half* __restrict__ A, const __half* __restrict__ Bv,
           __half* __restrict__ Ch,
           int K, long ldA, long ldB, long ldC,
           long sA, long sB, long sC)
{
    extern __shared__ char smem[];
    const uint32_t sb = smem_u32(smem);
    const int tid  = threadIdx.x;
    const int wid  = tid >> 5;
    const int lane = tid & 31;
    const long z   = blockIdx.z;

    // ---- loaders: 1024 chunks/stage (A: 512, B: 512), 4 per thread.
    // A chunk advances 64B of K per stage; B chunk advances 32 rows per stage.
    const long rowA = (long)blockIdx.y * 128;
    const long colB = (long)blockIdx.x * 128;     // n offset
    const char* gp[4];
    uint32_t sw[4];
    long st[4];
    #pragma unroll
    for (int j = 0; j < 4; j++) {
        int c = tid + 256 * j;
        if (c < 512) {
            int r = c >> 2;
            int col = (c & 3) * 16;
            sw[j] = (uint32_t)(r * ROWB + col);
            gp[j] = (const char*)(A + z * sA + (rowA + r) * ldA) + col;
            st[j] = 64;
        } else {
            int i2 = c - 512;
            int kr = i2 >> 4;                     // 0..31
            int nc16 = (i2 & 15) * 16;            // byte col in 256B row
            sw[j] = (uint32_t)(TOFFB + kr * BPITCH + nc16);
            gp[j] = (const char*)(Bv + z * sB + (long)kr * ldB + colB) + nc16;
            st[j] = 64 * ldB;                     // 32 rows * ldB * 2B
        }
    }

    // ---- fragment geometry
    const int warp_m = wid & 3;
    const int warp_n = wid >> 2;
    const int quad = lane >> 3;
    const int lr8  = lane & 7;
    const uint32_t aBase = sb + (uint32_t)((warp_m * 32 + lr8 + (quad & 1) * 8) * ROWB
                                           + (quad >> 1) * 16);
    // trans-B: lane addr -> stored row k = (quad>>1)*8 + lr8,
    //          byte col n = (warp_n*64 + (quad&1)*8)*2
    const uint32_t bBase = sb + TOFFB
        + (uint32_t)(((quad >> 1) * 8 + lr8) * BPITCH
                     + (warp_n * 64 + (quad & 1) * 8) * 2);

    float acc[2][8][4];
    #pragma unroll
    for (int mf = 0; mf < 2; mf++)
        #pragma unroll
        for (int nf = 0; nf < 8; nf++)
            #pragma unroll
            for (int q = 0; q < 4; q++) acc[mf][nf][q] = 0.f;

    const int nc = K >> 5;

#define LOADSTAGET(base, i) do { \
    _Pragma("unroll") \
    for (int j = 0; j < 4; j++) CP16((base) + sw[j], gp[j] + (long)(i) * st[j]); \
    asm volatile("cp.async.commit_group;" ::: "memory"); \
} while (0)

    LOADSTAGET(sb, 0);
    LOADSTAGET(sb + TSTAGE, 1);

    for (int i = 0; i < nc; i++) {
        if (i + 2 < nc) {
            LOADSTAGET(sb + ((i + 2) & 3) * TSTAGE, i + 2);
            asm volatile("cp.async.wait_group 2;" ::: "memory");
        } else if (i + 1 < nc) {
            asm volatile("cp.async.wait_group 1;" ::: "memory");
        } else {
            asm volatile("cp.async.wait_group 0;" ::: "memory");
        }
        __syncthreads();

        const uint32_t stA = aBase + (i & 3) * TSTAGE;
        const uint32_t stB = bBase + (i & 3) * TSTAGE;

        uint32_t ah[2][2][4], bh[2][4][4];
        #pragma unroll
        for (int ks = 0; ks < 2; ks++) {
            #pragma unroll
            for (int mf = 0; mf < 2; mf++)
                LDMX4(ah[ks][mf], stA + mf * (16 * ROWB) + ks * 32);
            #pragma unroll
            for (int ng = 0; ng < 4; ng++)
                LDMX4T(bh[ks][ng], stB + ks * (16 * BPITCH) + ng * 32);
        }
        #pragma unroll
        for (int ks = 0; ks < 2; ks++)
            #pragma unroll
            for (int ng = 0; ng < 4; ng++)
                #pragma unroll
                for (int mf = 0; mf < 2; mf++) {
                    MMA_F16(acc[mf][ng * 2 + 0], ah[ks][mf],
                            bh[ks][ng][0], bh[ks][ng][2]);
                    MMA_F16(acc[mf][ng * 2 + 1], ah[ks][mf],
                            bh[ks][ng][1], bh[ks][ng][3]);
                }
    }
#undef LOADSTAGET

    const long baseM = (long)blockIdx.y * 128 + warp_m * 32;
    const long baseN = (long)blockIdx.x * 128 + warp_n * 64;
    const int rq = lane >> 2;
    const int cq = (lane & 3) * 2;
    #pragma unroll
    for (int mf = 0; mf < 2; mf++) {
        #pragma unroll
        for (int nf = 0; nf < 8; nf++) {
            const long r0 = baseM + mf * 16 + rq;
            const long c0 = baseN + nf * 8 + cq;
            __half* oh0 = Ch + z * sC + r0 * ldC + c0;
            *(__half2*)oh0 = __halves2half2(__float2half_rn(acc[mf][nf][0]),
                                            __float2half_rn(acc[mf][nf][1]));
            *(__half2*)(oh0 + 8 * ldC) =
                __halves2half2(__float2half_rn(acc[mf][nf][2]),
                               __float2half_rn(acc[mf][nf][3]));
        }
    }
}

// ---------------------------------------------------------------------------
// Fused prep: X fp32->fp16 convert + 4 weight transposes, one launch.
// ---------------------------------------------------------------------------
__global__ __launch_bounds__(256)
void prep(const float* __restrict__ X,
          const float* __restrict__ WQ, const float* __restrict__ WK,
          const float* __restrict__ WV, const float* __restrict__ WO,
          __half* __restrict__ Xh, __half* __restrict__ Wqkvt,
          __half* __restrict__ WOt)
{
    __shared__ float t[32][33];
    const int bid = blockIdx.x;
    const int tid = threadIdx.x;

    if (bid < 8192) {
        int i = bid * 256 + tid;
        float4 v = ((const float4*)X)[i];
        ((__half2*)Xh)[2 * i]     = __halves2half2(__float2half_rn(v.x),
                                                   __float2half_rn(v.y));
        ((__half2*)Xh)[2 * i + 1] = __halves2half2(__float2half_rn(v.z),
                                                   __float2half_rn(v.w));
        return;
    }

    const int wb = bid - 8192;
    const int wi = wb >> 10;
    const int b  = wb & 1023;
    const float* src = (wi == 0) ? WQ : (wi == 1) ? WK : (wi == 2) ? WV : WO;
    __half* dst = (wi == 3) ? WOt : (Wqkvt + (long)wi * D_ * D_);

    const int c0 = (b & 31) * 32, r0 = (b >> 5) * 32;
    const int tx = tid & 31, ty = tid >> 5;
    #pragma unroll
    for (int j = 0; j < 4; j++)
        t[ty + 8 * j][tx] = src[(long)(r0 + ty + 8 * j) * D_ + c0 + tx];
    __syncthreads();
    #pragma unroll
    for (int j = 0; j < 4; j++)
        dst[(long)(c0 + ty + 8 * j) * D_ + r0 + tx] =
            __float2half_rn(t[tx][ty + 8 * j]);
}

// ---------------------------------------------------------------------------
// Row softmax over length-2048 rows; fp16 in (scaled logits), fp16 out.
// ---------------------------------------------------------------------------
__global__ __launch_bounds__(256)
void softmax_rows(const __half* __restrict__ Sh, __half* __restrict__ P)
{
    const long base = (long)blockIdx.x * S_;
    const uint2* row2 = (const uint2*)(Sh + base);
    const int tid  = threadIdx.x;
    const int lane = tid & 31;
    const int warp = tid >> 5;
    __shared__ float red[8];

    uint2 ua = row2[tid];
    uint2 ub = row2[tid + 256];
    float2 a0 = __half22float2(*(const __half2*)&ua.x);
    float2 a1 = __half22float2(*(const __half2*)&ua.y);
    float2 b0 = __half22float2(*(const __half2*)&ub.x);
    float2 b1 = __half22float2(*(const __half2*)&ub.y);

    float m = fmaxf(fmaxf(fmaxf(a0.x, a0.y), fmaxf(a1.x, a1.y)),
                    fmaxf(fmaxf(b0.x, b0.y), fmaxf(b1.x, b1.y)));
    #pragma unroll
    for (int o = 16; o > 0; o >>= 1) m = fmaxf(m, __shfl_xor_sync(0xffffffffu, m, o));
    if (lane == 0) red[warp] = m;
    __syncthreads();
    m = red[lane & 7];
    #pragma unroll
    for (int o = 4; o > 0; o >>= 1) m = fmaxf(m, __shfl_xor_sync(0xffffffffu, m, o));
    m = __shfl_sync(0xffffffffu, m, 0);

    a0.x = __expf(a0.x - m); a0.y = __expf(a0.y - m);
    a1.x = __expf(a1.x - m); a1.y = __expf(a1.y - m);
    b0.x = __expf(b0.x - m); b0.y = __expf(b0.y - m);
    b1.x = __expf(b1.x - m); b1.y = __expf(b1.y - m);
    float s = a0.x + a0.y + a1.x + a1.y + b0.x + b0.y + b1.x + b1.y;
    #pragma unroll
    for (int o = 16; o > 0; o >>= 1) s += __shfl_xor_sync(0xffffffffu, s, o);
    __syncthreads();
    if (lane == 0) red[warp] = s;
    __syncthreads();
    s = red[lane & 7];
    #pragma unroll
    for (int o = 4; o > 0; o >>= 1) s += __shfl_xor_sync(0xffffffffu, s, o);
    s = __shfl_sync(0xffffffffu, s, 0);

    const float inv = 1.f / s;
    __half2* p2 = (__half2*)(P + base);
    p2[2 * tid]       = __halves2half2(__float2half_rn(a0.x * inv),
                                       __float2half_rn(a0.y * inv));
    p2[2 * tid + 1]   = __halves2half2(__float2half_rn(a1.x * inv),
                                       __float2half_rn(a1.y * inv));
    p2[2 * (tid+256)]     = __halves2half2(__float2half_rn(b0.x * inv),
                                           __float2half_rn(b0.y * inv));
    p2[2 * (tid+256) + 1] = __halves2half2(__float2half_rn(b1.x * inv),
                                           __float2half_rn(b1.y * inv));
}

// ---------------------------------------------------------------------------
extern "C" void kernel_launch(void* const* d_in, const int* in_sizes, int n_in,
                              void* d_out, int out_size)
{
    const float* X  = (const float*)d_in[0];
    const float* WQ = (const float*)d_in[1];
    const float* WK = (const float*)d_in[2];
    const float* WV = (const float*)d_in[3];
    const float* WO = (const float*)d_in[4];
    float* Y = (float*)d_out;

    __half *Xh, *Wqkvt, *WOt, *QKV, *Sch, *Ph, *Hh;
    cudaGetSymbolAddress((void**)&Xh,    g_Xh);
    cudaGetSymbolAddress((void**)&Wqkvt, g_Wqkvt);
    cudaGetSymbolAddress((void**)&WOt,   g_WOt);
    cudaGetSymbolAddress((void**)&QKV,   g_QKV);
    cudaGetSymbolAddress((void**)&Sch,   g_Sch);
    cudaGetSymbolAddress((void**)&Ph,    g_Ph);
    cudaGetSymbolAddress((void**)&Hh,    g_Hh);

    cudaFuncSetAttribute(gemmh, cudaFuncAttributeMaxDynamicSharedMemorySize,
                         GEMM_SMEM);
    cudaFuncSetAttribute(gemmt, cudaFuncAttributeMaxDynamicSharedMemorySize,
                         GEMMT_SMEM);

    dim3 thr(256);
    const long LD3 = 3 * D_;                  // 3072

    // Fused input conversions (X convert + 4 W transposes)
    prep<<<8192 + 4096, thr>>>(X, WQ, WK, WV, WO, Xh, Wqkvt, WOt);

    // Fused QKV projection: [8192, 3072] = Xh · Wqkvt^T, fp16 out
    gemmh<<<dim3(24, 64, 1), thr, GEMM_SMEM>>>(Xh, Wqkvt, nullptr, QKV,
                                               D_, D_, D_, LD3,
                                               0, 0, 0, 1.f, 2);

    // Scores: per-batch [2048,2048] = Q · K^T / 32 -> fp16
    gemmh<<<dim3(16, 16, 4), thr, GEMM_SMEM>>>(QKV, QKV + D_, nullptr, Sch,
                                               D_, LD3, LD3, S_,
                                               (long)S_ * LD3, (long)S_ * LD3,
                                               (long)S_ * S_, 1.f / 32.f, 2);

    // Softmax (fp16 in) -> probs fp16
    softmax_rows<<<B_ * S_, thr>>>(Sch, Ph);

    // H = P · V : per-batch [2048,1024]; V read in place from QKV (trans-B)
    gemmt<<<dim3(8, 16, 4), thr, GEMMT_SMEM>>>(Ph, QKV + 2 * D_, Hh,
                                               S_, S_, LD3, D_,
                                               (long)S_ * S_, (long)S_ * LD3,
                                               (long)S_ * D_);

    // Output: [8192,1024] = Hh · WOt^T -> fp32 to d_out
    gemmh<<<dim3(8, 64, 1), thr, GEMM_SMEM>>>(Hh, WOt, Y, nullptr,
                                              D_, D_, D_, D_,
                                              0, 0, 0, 1.f, 0);
}